// round 4
// baseline (speedup 1.0000x reference)
#include <cuda_runtime.h>

#define DD    128
#define NEV   4
#define NN    50000
#define EE    800000
#define ETOT  (EE + NN)
#define EPSF  1e-8f
#define NBLK  ((NN + 1023) / 1024)   // 49 scan blocks

// ---------------- device scratch (no allocations allowed) ----------------
// g_h layout: node-major interleaved h[n][e][d]  (row for (n,e) = g_h + (n*4+e)*128)
__device__ float    g_h[(size_t)NEV * NN * DD];    // 102.4 MB
__device__ float    g_ssrc[NN * NEV];              // interleaved [n][e]
__device__ float    g_sdst[NN * NEV];
__device__ unsigned g_max_enc[NEV];
// CSR build
__device__ int      g_cnt[NN];        // degree (incl self-loop)
__device__ int      g_rowptr[NN];     // exclusive scan of cnt
__device__ int      g_cursor[NN];     // fill cursors
__device__ int      g_csrdst[ETOT];   // dst per slot, grouped by src
__device__ int      g_bsum[NBLK + 1];
__device__ int      g_boff[NBLK + 1];

// monotone encode: preserves float ordering in unsigned space
__device__ __forceinline__ unsigned enc_f(float f) {
    unsigned u = __float_as_uint(f);
    return (u & 0x80000000u) ? ~u : (u | 0x80000000u);
}
__device__ __forceinline__ float dec_u(unsigned u) {
    return (u & 0x80000000u) ? __uint_as_float(u ^ 0x80000000u)
                             : __uint_as_float(~u);
}
__device__ __forceinline__ float lrelu(float v) { return v > 0.f ? v : 0.01f * v; }

// ---------------- K0: zero counters --------------------------------------
__global__ void __launch_bounds__(256) k_zero() {
    int i = blockIdx.x * blockDim.x + threadIdx.x;
    if (i < NN) g_cnt[i] = 0;
    if (i < NEV) g_max_enc[i] = 0u;
}

// ---------------- K1: h[n][e] = x[n] @ W[e] (tiled fp32 GEMM) ------------
__global__ void __launch_bounds__(256) k_gemm(const float* __restrict__ x,
                                              const float* __restrict__ w) {
    __shared__ float As[32][132];
    __shared__ float Bs[32][128];
    const int e  = blockIdx.y;
    const int n0 = blockIdx.x * 128;
    const float* W = w + e * DD * DD;
    const int tid = threadIdx.x;
    const int tx = tid & 15, ty = tid >> 4;

    float acc[8][8];
#pragma unroll
    for (int i = 0; i < 8; i++)
#pragma unroll
        for (int j = 0; j < 8; j++) acc[i][j] = 0.f;

    for (int k0 = 0; k0 < DD; k0 += 32) {
#pragma unroll
        for (int i = 0; i < 4; i++) {
            int idx = tid + i * 256;
            int m = idx >> 3, kk = (idx & 7) << 2;
            int n = n0 + m;
            float4 v = make_float4(0.f, 0.f, 0.f, 0.f);
            if (n < NN) v = *(const float4*)(x + n * DD + k0 + kk);
            As[kk + 0][m] = v.x;
            As[kk + 1][m] = v.y;
            As[kk + 2][m] = v.z;
            As[kk + 3][m] = v.w;
        }
#pragma unroll
        for (int i = 0; i < 4; i++) {
            int idx = tid + i * 256;
            int kk = idx >> 5, c = (idx & 31) << 2;
            *(float4*)&Bs[kk][c] = *(const float4*)(W + (k0 + kk) * DD + c);
        }
        __syncthreads();
#pragma unroll
        for (int k = 0; k < 32; k++) {
            float ra[8], rb[8];
            *(float4*)(ra)     = *(const float4*)&As[k][ty * 8];
            *(float4*)(ra + 4) = *(const float4*)&As[k][ty * 8 + 4];
            *(float4*)(rb)     = *(const float4*)&Bs[k][tx * 8];
            *(float4*)(rb + 4) = *(const float4*)&Bs[k][tx * 8 + 4];
#pragma unroll
            for (int i = 0; i < 8; i++)
#pragma unroll
                for (int j = 0; j < 8; j++) acc[i][j] += ra[i] * rb[j];
        }
        __syncthreads();
    }
#pragma unroll
    for (int i = 0; i < 8; i++) {
        int n = n0 + ty * 8 + i;
        if (n < NN) {
            // node-major interleaved: row (n,e)
            float* hp = g_h + ((size_t)(n * NEV + e)) * DD + tx * 8;
            *(float4*)hp       = make_float4(acc[i][0], acc[i][1], acc[i][2], acc[i][3]);
            *(float4*)(hp + 4) = make_float4(acc[i][4], acc[i][5], acc[i][6], acc[i][7]);
        }
    }
}

// ---------------- K2: s_src/s_dst = h · a1/a2 (warp per (n,e) row) -------
__global__ void __launch_bounds__(256) k_s(const float* __restrict__ a) {
    int wrp  = (blockIdx.x * blockDim.x + threadIdx.x) >> 5;
    int lane = threadIdx.x & 31;
    if (wrp >= NN * NEV) return;
    int e = wrp & 3;  // row wrp of g_h is (n, e=wrp&3)

    float4 v   = ((const float4*)(g_h + (size_t)wrp * DD))[lane];
    float4 va1 = ((const float4*)(a + e * 2 * DD))[lane];
    float4 va2 = ((const float4*)(a + e * 2 * DD + DD))[lane];
    float s1 = v.x * va1.x + v.y * va1.y + v.z * va1.z + v.w * va1.w;
    float s2 = v.x * va2.x + v.y * va2.y + v.z * va2.z + v.w * va2.w;
#pragma unroll
    for (int off = 16; off > 0; off >>= 1) {
        s1 += __shfl_xor_sync(0xffffffffu, s1, off);
        s2 += __shfl_xor_sync(0xffffffffu, s2, off);
    }
    if (lane == 0) {
        g_ssrc[wrp] = s1;   // interleaved [n*4+e]
        g_sdst[wrp] = s2;
    }
}

// ---------------- K3: degree histogram -----------------------------------
__global__ void __launch_bounds__(256) k_hist(const int* __restrict__ row) {
    int k = blockIdx.x * blockDim.x + threadIdx.x;
    if (k >= ETOT) return;
    int src = (k < EE) ? row[k] : (k - EE);
    atomicAdd(&g_cnt[src], 1);
}

// ---------------- K4a: per-block exclusive scan of g_cnt -----------------
__global__ void __launch_bounds__(1024) k_scan1() {
    int i = blockIdx.x * 1024 + threadIdx.x;
    int lane = threadIdx.x & 31, wid = threadIdx.x >> 5;
    int v = (i < NN) ? g_cnt[i] : 0;
    int s = v;
#pragma unroll
    for (int off = 1; off < 32; off <<= 1) {
        int t = __shfl_up_sync(0xffffffffu, s, off);
        if (lane >= off) s += t;
    }
    __shared__ int wsum[32];
    if (lane == 31) wsum[wid] = s;
    __syncthreads();
    if (wid == 0) {
        int t = wsum[lane];
        int sc = t;
#pragma unroll
        for (int off = 1; off < 32; off <<= 1) {
            int u = __shfl_up_sync(0xffffffffu, sc, off);
            if (lane >= off) sc += u;
        }
        wsum[lane] = sc - t;  // exclusive
    }
    __syncthreads();
    int excl = s - v + wsum[wid];
    if (i < NN) g_rowptr[i] = excl;
    if (threadIdx.x == 1023) g_bsum[blockIdx.x] = excl + v;
}

// ---------------- K4b: scan block sums (tiny, serial) --------------------
__global__ void k_scan2() {
    if (threadIdx.x == 0) {
        int run = 0;
        for (int i = 0; i < NBLK; i++) {
            int t = g_bsum[i];
            g_boff[i] = run;
            run += t;
        }
    }
}

// ---------------- K4c: add block offsets, init cursors -------------------
__global__ void __launch_bounds__(1024) k_scan3() {
    int i = blockIdx.x * 1024 + threadIdx.x;
    if (i < NN) {
        int r = g_rowptr[i] + g_boff[i >> 10];
        g_rowptr[i] = r;
        g_cursor[i] = r;
    }
}

// ---------------- K5: CSR fill -------------------------------------------
__global__ void __launch_bounds__(256) k_fill(const int* __restrict__ row,
                                              const int* __restrict__ col) {
    int k = blockIdx.x * blockDim.x + threadIdx.x;
    if (k >= ETOT) return;
    int src, dst;
    if (k < EE) { src = row[k]; dst = col[k]; }
    else        { src = dst = k - EE; }
    int slot = atomicAdd(&g_cursor[src], 1);
    g_csrdst[slot] = dst;
}

// ---------------- K6: per-env global max of leaky logits -----------------
__global__ void __launch_bounds__(256) k_max(const int* __restrict__ row,
                                             const int* __restrict__ col) {
    float m0 = -3.4e38f, m1 = -3.4e38f, m2 = -3.4e38f, m3 = -3.4e38f;
    for (int k = blockIdx.x * blockDim.x + threadIdx.x; k < ETOT;
         k += gridDim.x * blockDim.x) {
        int src, dst;
        if (k < EE) { src = row[k]; dst = col[k]; }
        else        { src = dst = k - EE; }
        float4 sa = ((const float4*)g_ssrc)[src];
        float4 sb = ((const float4*)g_sdst)[dst];
        m0 = fmaxf(m0, lrelu(sa.x + sb.x));
        m1 = fmaxf(m1, lrelu(sa.y + sb.y));
        m2 = fmaxf(m2, lrelu(sa.z + sb.z));
        m3 = fmaxf(m3, lrelu(sa.w + sb.w));
    }
    int lane = threadIdx.x & 31, wid = threadIdx.x >> 5;
#pragma unroll
    for (int off = 16; off > 0; off >>= 1) {
        m0 = fmaxf(m0, __shfl_xor_sync(0xffffffffu, m0, off));
        m1 = fmaxf(m1, __shfl_xor_sync(0xffffffffu, m1, off));
        m2 = fmaxf(m2, __shfl_xor_sync(0xffffffffu, m2, off));
        m3 = fmaxf(m3, __shfl_xor_sync(0xffffffffu, m3, off));
    }
    __shared__ float sm[8][NEV];
    if (lane == 0) { sm[wid][0] = m0; sm[wid][1] = m1; sm[wid][2] = m2; sm[wid][3] = m3; }
    __syncthreads();
    if (threadIdx.x < NEV) {
        int e = threadIdx.x;
        float mm = -3.4e38f;
#pragma unroll
        for (int wdx = 0; wdx < 8; wdx++) mm = fmaxf(mm, sm[wdx][e]);
        atomicMax(&g_max_enc[e], enc_f(mm));
    }
}

// ---------------- K7: fused gather-aggregate + combine + residual --------
// one warp per node: loops its CSR edges, accumulates all 4 envs in regs,
// applies env weights, adds x, writes out. No atomics, no g_num.
__global__ void __launch_bounds__(256) k_agg(const float* __restrict__ x,
                                             const float* __restrict__ ew,
                                             float* __restrict__ out) {
    int n    = (blockIdx.x * blockDim.x + threadIdx.x) >> 5;
    int lane = threadIdx.x & 31;
    if (n >= NN) return;

    float4 ss = ((const float4*)g_ssrc)[n];
    float M0 = dec_u(g_max_enc[0]);
    float M1 = dec_u(g_max_enc[1]);
    float M2 = dec_u(g_max_enc[2]);
    float M3 = dec_u(g_max_enc[3]);

    int start = g_rowptr[n];
    int deg   = g_cnt[n];

    float4 a0 = make_float4(0.f, 0.f, 0.f, 0.f);
    float4 a1 = a0, a2 = a0, a3 = a0;
    float d0 = 0.f, d1 = 0.f, d2 = 0.f, d3 = 0.f;

#pragma unroll 4
    for (int j = 0; j < deg; j++) {
        int dst = g_csrdst[start + j];
        float4 sd = ((const float4*)g_sdst)[dst];
        float t0 = __expf(lrelu(ss.x + sd.x) - M0);
        float t1 = __expf(lrelu(ss.y + sd.y) - M1);
        float t2 = __expf(lrelu(ss.z + sd.z) - M2);
        float t3 = __expf(lrelu(ss.w + sd.w) - M3);

        const float4* hp = (const float4*)(g_h + (size_t)dst * (NEV * DD));
        float4 v0 = hp[lane];          // env 0: floats [0,128)
        float4 v1 = hp[32 + lane];     // env 1
        float4 v2 = hp[64 + lane];     // env 2
        float4 v3 = hp[96 + lane];     // env 3

        a0.x += t0 * v0.x; a0.y += t0 * v0.y; a0.z += t0 * v0.z; a0.w += t0 * v0.w;
        a1.x += t1 * v1.x; a1.y += t1 * v1.y; a1.z += t1 * v1.z; a1.w += t1 * v1.w;
        a2.x += t2 * v2.x; a2.y += t2 * v2.y; a2.z += t2 * v2.z; a2.w += t2 * v2.w;
        a3.x += t3 * v3.x; a3.y += t3 * v3.y; a3.z += t3 * v3.z; a3.w += t3 * v3.w;
        d0 += t0; d1 += t1; d2 += t2; d3 += t3;
    }

    float4 ewv = ((const float4*)ew)[n];
    float w0 = ewv.x / (d0 + EPSF);
    float w1 = ewv.y / (d1 + EPSF);
    float w2 = ewv.z / (d2 + EPSF);
    float w3 = ewv.w / (d3 + EPSF);

    float4 o = ((const float4*)x)[n * 32 + lane];
    o.x += w0 * a0.x + w1 * a1.x + w2 * a2.x + w3 * a3.x;
    o.y += w0 * a0.y + w1 * a1.y + w2 * a2.y + w3 * a3.y;
    o.z += w0 * a0.z + w1 * a1.z + w2 * a2.z + w3 * a3.z;
    o.w += w0 * a0.w + w1 * a1.w + w2 * a2.w + w3 * a3.w;
    ((float4*)out)[n * 32 + lane] = o;
}

// ---------------- launch --------------------------------------------------
extern "C" void kernel_launch(void* const* d_in, const int* in_sizes, int n_in,
                              void* d_out, int out_size) {
    const float* x   = (const float*)d_in[0];
    const int*   adj = (const int*)d_in[1];
    const float* ew  = (const float*)d_in[2];
    const float* w   = (const float*)d_in[3];
    const float* a   = (const float*)d_in[4];
    const int* row = adj;
    const int* col = adj + EE;
    float* out = (float*)d_out;

    k_zero<<<(NN + 255) / 256, 256>>>();

    dim3 g1((NN + 127) / 128, NEV);
    k_gemm<<<g1, 256>>>(x, w);

    k_s<<<(NN * NEV * 32 + 255) / 256, 256>>>(a);

    k_hist<<<(ETOT + 255) / 256, 256>>>(row);
    k_scan1<<<NBLK, 1024>>>();
    k_scan2<<<1, 32>>>();
    k_scan3<<<NBLK, 1024>>>();
    k_fill<<<(ETOT + 255) / 256, 256>>>(row, col);

    k_max<<<1024, 256>>>(row, col);

    k_agg<<<(NN * 32 + 255) / 256, 256>>>(x, ew, out);
}

// round 5
// speedup vs baseline: 1.4051x; 1.4051x over previous
#include <cuda_runtime.h>
#include <cstdint>

#define DD    128
#define NEV   4
#define NN    50000
#define EE    800000
#define ETOT  (EE + NN)
#define EPSF  1e-8f
#define NBLK  ((NN + 1023) / 1024)   // 49 scan blocks

// ---------------- device scratch (no allocations allowed) ----------------
// g_h layout: node-major interleaved h[n][e][d]  (row for (n,e) = g_h + (n*4+e)*128)
__device__ float    g_h[(size_t)NEV * NN * DD];    // 102.4 MB
__device__ float    g_ssrc[NN * NEV];              // interleaved [n][e]
__device__ float    g_sdst[NN * NEV];
__device__ unsigned g_max_enc[NEV];
// CSR build
__device__ int      g_cnt[NN];
__device__ int      g_rowptr[NN];
__device__ int      g_cursor[NN];
__device__ int      g_csrdst[ETOT];
__device__ int      g_bsum[NBLK + 1];
__device__ int      g_boff[NBLK + 1];

__device__ __forceinline__ unsigned enc_f(float f) {
    unsigned u = __float_as_uint(f);
    return (u & 0x80000000u) ? ~u : (u | 0x80000000u);
}
__device__ __forceinline__ float dec_u(unsigned u) {
    return (u & 0x80000000u) ? __uint_as_float(u ^ 0x80000000u)
                             : __uint_as_float(~u);
}
__device__ __forceinline__ float lrelu(float v) { return v > 0.f ? v : 0.01f * v; }
__device__ __forceinline__ uint32_t f2tf32(float f) {
    uint32_t u;
    asm("cvt.rna.tf32.f32 %0, %1;" : "=r"(u) : "f"(f));
    return u;
}

// ---------------- K0: zero counters --------------------------------------
__global__ void __launch_bounds__(256) k_zero() {
    int i = blockIdx.x * blockDim.x + threadIdx.x;
    if (i < NN) g_cnt[i] = 0;
    if (i < NEV) g_max_enc[i] = 0u;
}

// ---------------- K1: tf32 MMA GEMM + fused s epilogue -------------------
// block: 128 rows (n) x 128 cols (f) for one env. 8 warps in 4(m) x 2(n).
// warp tile 32x64 = 2 (m16) x 8 (n8) mma frags. K looped 4 x 32 (4 x k8 sub).
__global__ void __launch_bounds__(256) k_gemm(const float* __restrict__ x,
                                              const float* __restrict__ w,
                                              const float* __restrict__ a) {
    __shared__ float As[128][36];   // stride 36: frag loads conflict-free
    __shared__ float Bs[32][136];   // stride 136
    __shared__ float s1_sm[128], s2_sm[128];
    __shared__ float a_sm[2][128];

    const int e   = blockIdx.y;
    const int n0  = blockIdx.x * 128;
    const int tid = threadIdx.x;
    const int lane = tid & 31, wid = tid >> 5;
    const int wm = wid & 3;      // warp row 0..3  (rows wm*32..wm*32+31)
    const int wn = wid >> 2;     // warp col 0..1  (cols wn*64..wn*64+63)
    const int qid = lane >> 2;   // 0..7
    const int qtr = lane & 3;    // 0..3

    if (tid < 128) {
        a_sm[0][tid] = a[e * 2 * DD + tid];
        a_sm[1][tid] = a[e * 2 * DD + DD + tid];
        s1_sm[tid] = 0.f;
        s2_sm[tid] = 0.f;
    }

    float c[2][8][4];
#pragma unroll
    for (int mi = 0; mi < 2; mi++)
#pragma unroll
        for (int ni = 0; ni < 8; ni++)
#pragma unroll
            for (int q = 0; q < 4; q++) c[mi][ni][q] = 0.f;

    const float* W = w + e * DD * DD;

    for (int k0 = 0; k0 < DD; k0 += 32) {
#pragma unroll
        for (int i = 0; i < 4; i++) {
            int idx = tid + i * 256;           // float4 unit 0..1023
            int row = idx >> 3, col4 = (idx & 7) << 2;
            float4 v = make_float4(0.f, 0.f, 0.f, 0.f);
            if (n0 + row < NN) v = *(const float4*)(x + (size_t)(n0 + row) * DD + k0 + col4);
            As[row][col4 + 0] = __uint_as_float(f2tf32(v.x));
            As[row][col4 + 1] = __uint_as_float(f2tf32(v.y));
            As[row][col4 + 2] = __uint_as_float(f2tf32(v.z));
            As[row][col4 + 3] = __uint_as_float(f2tf32(v.w));
        }
#pragma unroll
        for (int i = 0; i < 4; i++) {
            int idx = tid + i * 256;
            int kk = idx >> 5, c4 = (idx & 31) << 2;
            float4 v = *(const float4*)(W + (size_t)(k0 + kk) * DD + c4);
            Bs[kk][c4 + 0] = __uint_as_float(f2tf32(v.x));
            Bs[kk][c4 + 1] = __uint_as_float(f2tf32(v.y));
            Bs[kk][c4 + 2] = __uint_as_float(f2tf32(v.z));
            Bs[kk][c4 + 3] = __uint_as_float(f2tf32(v.w));
        }
        __syncthreads();

#pragma unroll
        for (int ks = 0; ks < 4; ks++) {
            const int kb = ks * 8;
            uint32_t af[2][4];
#pragma unroll
            for (int mi = 0; mi < 2; mi++) {
                int r = wm * 32 + mi * 16 + qid;
                af[mi][0] = __float_as_uint(As[r][kb + qtr]);
                af[mi][1] = __float_as_uint(As[r + 8][kb + qtr]);
                af[mi][2] = __float_as_uint(As[r][kb + qtr + 4]);
                af[mi][3] = __float_as_uint(As[r + 8][kb + qtr + 4]);
            }
            uint32_t bf[8][2];
#pragma unroll
            for (int ni = 0; ni < 8; ni++) {
                int ncol = wn * 64 + ni * 8 + qid;
                bf[ni][0] = __float_as_uint(Bs[kb + qtr][ncol]);
                bf[ni][1] = __float_as_uint(Bs[kb + qtr + 4][ncol]);
            }
#pragma unroll
            for (int mi = 0; mi < 2; mi++)
#pragma unroll
                for (int ni = 0; ni < 8; ni++)
                    asm volatile(
                        "mma.sync.aligned.m16n8k8.row.col.f32.tf32.tf32.f32 "
                        "{%0,%1,%2,%3}, {%4,%5,%6,%7}, {%8,%9}, {%0,%1,%2,%3};"
                        : "+f"(c[mi][ni][0]), "+f"(c[mi][ni][1]),
                          "+f"(c[mi][ni][2]), "+f"(c[mi][ni][3])
                        : "r"(af[mi][0]), "r"(af[mi][1]), "r"(af[mi][2]), "r"(af[mi][3]),
                          "r"(bf[ni][0]), "r"(bf[ni][1]));
        }
        __syncthreads();
    }

    // ---- epilogue: store g_h + fused s = h·a1 / h·a2 ----
#pragma unroll
    for (int mi = 0; mi < 2; mi++) {
        int rA = wm * 32 + mi * 16 + qid;      // rows rA (c0,c1) and rA+8 (c2,c3)
        float s1a = 0.f, s2a = 0.f, s1b = 0.f, s2b = 0.f;
#pragma unroll
        for (int ni = 0; ni < 8; ni++) {
            int cb = wn * 64 + ni * 8 + 2 * qtr;
            float c0 = c[mi][ni][0], c1 = c[mi][ni][1];
            float c2 = c[mi][ni][2], c3 = c[mi][ni][3];
            if (n0 + rA < NN) {
                float2* hp = (float2*)(g_h + ((size_t)((n0 + rA) * NEV + e)) * DD + cb);
                *hp = make_float2(c0, c1);
            }
            if (n0 + rA + 8 < NN) {
                float2* hp = (float2*)(g_h + ((size_t)((n0 + rA + 8) * NEV + e)) * DD + cb);
                *hp = make_float2(c2, c3);
            }
            float a10 = a_sm[0][cb], a11 = a_sm[0][cb + 1];
            float a20 = a_sm[1][cb], a21 = a_sm[1][cb + 1];
            s1a += c0 * a10 + c1 * a11;
            s2a += c0 * a20 + c1 * a21;
            s1b += c2 * a10 + c3 * a11;
            s2b += c2 * a20 + c3 * a21;
        }
        // reduce over the 4 lanes sharing each row (qtr dimension)
#pragma unroll
        for (int off = 1; off < 4; off <<= 1) {
            s1a += __shfl_xor_sync(0xffffffffu, s1a, off);
            s2a += __shfl_xor_sync(0xffffffffu, s2a, off);
            s1b += __shfl_xor_sync(0xffffffffu, s1b, off);
            s2b += __shfl_xor_sync(0xffffffffu, s2b, off);
        }
        if (qtr == 0) {
            atomicAdd(&s1_sm[rA], s1a);
            atomicAdd(&s2_sm[rA], s2a);
            atomicAdd(&s1_sm[rA + 8], s1b);
            atomicAdd(&s2_sm[rA + 8], s2b);
        }
    }
    __syncthreads();
    if (tid < 128 && n0 + tid < NN) {
        g_ssrc[(n0 + tid) * NEV + e] = s1_sm[tid];
        g_sdst[(n0 + tid) * NEV + e] = s2_sm[tid];
    }
}

// ---------------- K3: degree histogram -----------------------------------
__global__ void __launch_bounds__(256) k_hist(const int* __restrict__ row) {
    int k = blockIdx.x * blockDim.x + threadIdx.x;
    if (k >= ETOT) return;
    int src = (k < EE) ? row[k] : (k - EE);
    atomicAdd(&g_cnt[src], 1);
}

// ---------------- K4a: per-block exclusive scan of g_cnt -----------------
__global__ void __launch_bounds__(1024) k_scan1() {
    int i = blockIdx.x * 1024 + threadIdx.x;
    int lane = threadIdx.x & 31, wid = threadIdx.x >> 5;
    int v = (i < NN) ? g_cnt[i] : 0;
    int s = v;
#pragma unroll
    for (int off = 1; off < 32; off <<= 1) {
        int t = __shfl_up_sync(0xffffffffu, s, off);
        if (lane >= off) s += t;
    }
    __shared__ int wsum[32];
    if (lane == 31) wsum[wid] = s;
    __syncthreads();
    if (wid == 0) {
        int t = wsum[lane];
        int sc = t;
#pragma unroll
        for (int off = 1; off < 32; off <<= 1) {
            int u = __shfl_up_sync(0xffffffffu, sc, off);
            if (lane >= off) sc += u;
        }
        wsum[lane] = sc - t;
    }
    __syncthreads();
    int excl = s - v + wsum[wid];
    if (i < NN) g_rowptr[i] = excl;
    if (threadIdx.x == 1023) g_bsum[blockIdx.x] = excl + v;
}

// ---------------- K4b: scan block sums -----------------------------------
__global__ void k_scan2() {
    if (threadIdx.x == 0) {
        int run = 0;
        for (int i = 0; i < NBLK; i++) {
            int t = g_bsum[i];
            g_boff[i] = run;
            run += t;
        }
    }
}

// ---------------- K4c: add block offsets, init cursors -------------------
__global__ void __launch_bounds__(1024) k_scan3() {
    int i = blockIdx.x * 1024 + threadIdx.x;
    if (i < NN) {
        int r = g_rowptr[i] + g_boff[i >> 10];
        g_rowptr[i] = r;
        g_cursor[i] = r;
    }
}

// ---------------- K5: CSR fill -------------------------------------------
__global__ void __launch_bounds__(256) k_fill(const int* __restrict__ row,
                                              const int* __restrict__ col) {
    int k = blockIdx.x * blockDim.x + threadIdx.x;
    if (k >= ETOT) return;
    int src, dst;
    if (k < EE) { src = row[k]; dst = col[k]; }
    else        { src = dst = k - EE; }
    int slot = atomicAdd(&g_cursor[src], 1);
    g_csrdst[slot] = dst;
}

// ---------------- K6: per-env global max of leaky logits -----------------
__global__ void __launch_bounds__(256) k_max(const int* __restrict__ row,
                                             const int* __restrict__ col) {
    float m0 = -3.4e38f, m1 = -3.4e38f, m2 = -3.4e38f, m3 = -3.4e38f;
    for (int k = blockIdx.x * blockDim.x + threadIdx.x; k < ETOT;
         k += gridDim.x * blockDim.x) {
        int src, dst;
        if (k < EE) { src = row[k]; dst = col[k]; }
        else        { src = dst = k - EE; }
        float4 sa = ((const float4*)g_ssrc)[src];
        float4 sb = ((const float4*)g_sdst)[dst];
        m0 = fmaxf(m0, lrelu(sa.x + sb.x));
        m1 = fmaxf(m1, lrelu(sa.y + sb.y));
        m2 = fmaxf(m2, lrelu(sa.z + sb.z));
        m3 = fmaxf(m3, lrelu(sa.w + sb.w));
    }
    int lane = threadIdx.x & 31, wid = threadIdx.x >> 5;
#pragma unroll
    for (int off = 16; off > 0; off >>= 1) {
        m0 = fmaxf(m0, __shfl_xor_sync(0xffffffffu, m0, off));
        m1 = fmaxf(m1, __shfl_xor_sync(0xffffffffu, m1, off));
        m2 = fmaxf(m2, __shfl_xor_sync(0xffffffffu, m2, off));
        m3 = fmaxf(m3, __shfl_xor_sync(0xffffffffu, m3, off));
    }
    __shared__ float sm[8][NEV];
    if (lane == 0) { sm[wid][0] = m0; sm[wid][1] = m1; sm[wid][2] = m2; sm[wid][3] = m3; }
    __syncthreads();
    if (threadIdx.x < NEV) {
        int e = threadIdx.x;
        float mm = -3.4e38f;
#pragma unroll
        for (int wdx = 0; wdx < 8; wdx++) mm = fmaxf(mm, sm[wdx][e]);
        atomicMax(&g_max_enc[e], enc_f(mm));
    }
}

// ---------------- K7: fused gather-aggregate + combine + residual --------
__global__ void __launch_bounds__(256) k_agg(const float* __restrict__ x,
                                             const float* __restrict__ ew,
                                             float* __restrict__ out) {
    int n    = (blockIdx.x * blockDim.x + threadIdx.x) >> 5;
    int lane = threadIdx.x & 31;
    if (n >= NN) return;

    float4 ss = ((const float4*)g_ssrc)[n];
    float M0 = dec_u(g_max_enc[0]);
    float M1 = dec_u(g_max_enc[1]);
    float M2 = dec_u(g_max_enc[2]);
    float M3 = dec_u(g_max_enc[3]);

    int start = g_rowptr[n];
    int deg   = g_cnt[n];

    float4 a0 = make_float4(0.f, 0.f, 0.f, 0.f);
    float4 a1 = a0, a2 = a0, a3 = a0;
    float d0 = 0.f, d1 = 0.f, d2 = 0.f, d3 = 0.f;

#pragma unroll 4
    for (int j = 0; j < deg; j++) {
        int dst = g_csrdst[start + j];
        float4 sd = ((const float4*)g_sdst)[dst];
        float t0 = __expf(lrelu(ss.x + sd.x) - M0);
        float t1 = __expf(lrelu(ss.y + sd.y) - M1);
        float t2 = __expf(lrelu(ss.z + sd.z) - M2);
        float t3 = __expf(lrelu(ss.w + sd.w) - M3);

        const float4* hp = (const float4*)(g_h + (size_t)dst * (NEV * DD));
        float4 v0 = hp[lane];
        float4 v1 = hp[32 + lane];
        float4 v2 = hp[64 + lane];
        float4 v3 = hp[96 + lane];

        a0.x += t0 * v0.x; a0.y += t0 * v0.y; a0.z += t0 * v0.z; a0.w += t0 * v0.w;
        a1.x += t1 * v1.x; a1.y += t1 * v1.y; a1.z += t1 * v1.z; a1.w += t1 * v1.w;
        a2.x += t2 * v2.x; a2.y += t2 * v2.y; a2.z += t2 * v2.z; a2.w += t2 * v2.w;
        a3.x += t3 * v3.x; a3.y += t3 * v3.y; a3.z += t3 * v3.z; a3.w += t3 * v3.w;
        d0 += t0; d1 += t1; d2 += t2; d3 += t3;
    }

    float4 ewv = ((const float4*)ew)[n];
    float w0 = ewv.x / (d0 + EPSF);
    float w1 = ewv.y / (d1 + EPSF);
    float w2 = ewv.z / (d2 + EPSF);
    float w3 = ewv.w / (d3 + EPSF);

    float4 o = ((const float4*)x)[n * 32 + lane];
    o.x += w0 * a0.x + w1 * a1.x + w2 * a2.x + w3 * a3.x;
    o.y += w0 * a0.y + w1 * a1.y + w2 * a2.y + w3 * a3.y;
    o.z += w0 * a0.z + w1 * a1.z + w2 * a2.z + w3 * a3.z;
    o.w += w0 * a0.w + w1 * a1.w + w2 * a2.w + w3 * a3.w;
    ((float4*)out)[n * 32 + lane] = o;
}

// ---------------- launch --------------------------------------------------
extern "C" void kernel_launch(void* const* d_in, const int* in_sizes, int n_in,
                              void* d_out, int out_size) {
    const float* x   = (const float*)d_in[0];
    const int*   adj = (const int*)d_in[1];
    const float* ew  = (const float*)d_in[2];
    const float* w   = (const float*)d_in[3];
    const float* a   = (const float*)d_in[4];
    const int* row = adj;
    const int* col = adj + EE;
    float* out = (float*)d_out;

    k_zero<<<(NN + 255) / 256, 256>>>();

    dim3 g1((NN + 127) / 128, NEV);
    k_gemm<<<g1, 256>>>(x, w, a);

    k_hist<<<(ETOT + 255) / 256, 256>>>(row);
    k_scan1<<<NBLK, 1024>>>();
    k_scan2<<<1, 32>>>();
    k_scan3<<<NBLK, 1024>>>();
    k_fill<<<(ETOT + 255) / 256, 256>>>(row, col);

    k_max<<<1024, 256>>>(row, col);

    k_agg<<<(NN * 32 + 255) / 256, 256>>>(x, ew, out);
}

// round 7
// speedup vs baseline: 1.8579x; 1.3222x over previous
#include <cuda_runtime.h>
#include <cuda_bf16.h>
#include <cstdint>

#define DD    128
#define NEV   4
#define NN    50000
#define EE    800000
#define ETOT  (EE + NN)
#define EPSF  1e-8f
#define NBLK  ((NN + 1023) / 1024)   // 49 scan blocks

// ---------------- device scratch (no allocations allowed) ----------------
// g_hb layout: node-major interleaved bf16 h[n][e][d] (row (n,e) = g_hb+(n*4+e)*128)
__device__ __nv_bfloat16 g_hb[(size_t)NEV * NN * DD];  // 51.2 MB
__device__ float    g_ssrc[NN * NEV];                  // interleaved [n][e]
__device__ float    g_sdst[NN * NEV];
__device__ unsigned g_max_enc[NEV];
// CSR build
__device__ int      g_cnt[NN];
__device__ int      g_rowptr[NN];
__device__ int      g_cursor[NN];
__device__ int      g_csrdst[ETOT];
__device__ int      g_bsum[NBLK + 1];
__device__ int      g_boff[NBLK + 1];

__device__ __forceinline__ unsigned enc_f(float f) {
    unsigned u = __float_as_uint(f);
    return (u & 0x80000000u) ? ~u : (u | 0x80000000u);
}
__device__ __forceinline__ float dec_u(unsigned u) {
    return (u & 0x80000000u) ? __uint_as_float(u ^ 0x80000000u)
                             : __uint_as_float(~u);
}
__device__ __forceinline__ float lrelu(float v) { return v > 0.f ? v : 0.01f * v; }
__device__ __forceinline__ uint32_t f2tf32(float f) {
    uint32_t u;
    asm("cvt.rna.tf32.f32 %0, %1;" : "=r"(u) : "f"(f));
    return u;
}

// ---------------- K0: zero counters --------------------------------------
__global__ void __launch_bounds__(256) k_zero() {
    int i = blockIdx.x * blockDim.x + threadIdx.x;
    if (i < NN) g_cnt[i] = 0;
    if (i < NEV) g_max_enc[i] = 0u;
}

// ---------------- K1: tf32 MMA GEMM + fused s epilogue, bf16 h store -----
__global__ void __launch_bounds__(256) k_gemm(const float* __restrict__ x,
                                              const float* __restrict__ w,
                                              const float* __restrict__ a) {
    __shared__ float As[128][36];
    __shared__ float Bs[32][136];
    __shared__ float s1_sm[128], s2_sm[128];
    __shared__ float a_sm[2][128];

    const int e   = blockIdx.y;
    const int n0  = blockIdx.x * 128;
    const int tid = threadIdx.x;
    const int lane = tid & 31, wid = tid >> 5;
    const int wm = wid & 3;
    const int wn = wid >> 2;
    const int qid = lane >> 2;
    const int qtr = lane & 3;

    if (tid < 128) {
        a_sm[0][tid] = a[e * 2 * DD + tid];
        a_sm[1][tid] = a[e * 2 * DD + DD + tid];
        s1_sm[tid] = 0.f;
        s2_sm[tid] = 0.f;
    }

    float c[2][8][4];
#pragma unroll
    for (int mi = 0; mi < 2; mi++)
#pragma unroll
        for (int ni = 0; ni < 8; ni++)
#pragma unroll
            for (int q = 0; q < 4; q++) c[mi][ni][q] = 0.f;

    const float* W = w + e * DD * DD;

    for (int k0 = 0; k0 < DD; k0 += 32) {
#pragma unroll
        for (int i = 0; i < 4; i++) {
            int idx = tid + i * 256;
            int row = idx >> 3, col4 = (idx & 7) << 2;
            float4 v = make_float4(0.f, 0.f, 0.f, 0.f);
            if (n0 + row < NN) v = *(const float4*)(x + (size_t)(n0 + row) * DD + k0 + col4);
            As[row][col4 + 0] = __uint_as_float(f2tf32(v.x));
            As[row][col4 + 1] = __uint_as_float(f2tf32(v.y));
            As[row][col4 + 2] = __uint_as_float(f2tf32(v.z));
            As[row][col4 + 3] = __uint_as_float(f2tf32(v.w));
        }
#pragma unroll
        for (int i = 0; i < 4; i++) {
            int idx = tid + i * 256;
            int kk = idx >> 5, c4 = (idx & 31) << 2;
            float4 v = *(const float4*)(W + (size_t)(k0 + kk) * DD + c4);
            Bs[kk][c4 + 0] = __uint_as_float(f2tf32(v.x));
            Bs[kk][c4 + 1] = __uint_as_float(f2tf32(v.y));
            Bs[kk][c4 + 2] = __uint_as_float(f2tf32(v.z));
            Bs[kk][c4 + 3] = __uint_as_float(f2tf32(v.w));
        }
        __syncthreads();

#pragma unroll
        for (int ks = 0; ks < 4; ks++) {
            const int kb = ks * 8;
            uint32_t af[2][4];
#pragma unroll
            for (int mi = 0; mi < 2; mi++) {
                int r = wm * 32 + mi * 16 + qid;
                af[mi][0] = __float_as_uint(As[r][kb + qtr]);
                af[mi][1] = __float_as_uint(As[r + 8][kb + qtr]);
                af[mi][2] = __float_as_uint(As[r][kb + qtr + 4]);
                af[mi][3] = __float_as_uint(As[r + 8][kb + qtr + 4]);
            }
            uint32_t bf[8][2];
#pragma unroll
            for (int ni = 0; ni < 8; ni++) {
                int ncol = wn * 64 + ni * 8 + qid;
                bf[ni][0] = __float_as_uint(Bs[kb + qtr][ncol]);
                bf[ni][1] = __float_as_uint(Bs[kb + qtr + 4][ncol]);
            }
#pragma unroll
            for (int mi = 0; mi < 2; mi++)
#pragma unroll
                for (int ni = 0; ni < 8; ni++)
                    asm volatile(
                        "mma.sync.aligned.m16n8k8.row.col.f32.tf32.tf32.f32 "
                        "{%0,%1,%2,%3}, {%4,%5,%6,%7}, {%8,%9}, {%0,%1,%2,%3};"
                        : "+f"(c[mi][ni][0]), "+f"(c[mi][ni][1]),
                          "+f"(c[mi][ni][2]), "+f"(c[mi][ni][3])
                        : "r"(af[mi][0]), "r"(af[mi][1]), "r"(af[mi][2]), "r"(af[mi][3]),
                          "r"(bf[ni][0]), "r"(bf[ni][1]));
        }
        __syncthreads();
    }

    // ---- epilogue: store bf16 h + fused s = h·a1 / h·a2 (from fp32 regs) ----
#pragma unroll
    for (int mi = 0; mi < 2; mi++) {
        int rA = wm * 32 + mi * 16 + qid;      // rows rA (c0,c1) and rA+8 (c2,c3)
        float s1a = 0.f, s2a = 0.f, s1b = 0.f, s2b = 0.f;
#pragma unroll
        for (int ni = 0; ni < 8; ni++) {
            int cb = wn * 64 + ni * 8 + 2 * qtr;
            float c0 = c[mi][ni][0], c1 = c[mi][ni][1];
            float c2 = c[mi][ni][2], c3 = c[mi][ni][3];
            if (n0 + rA < NN) {
                __nv_bfloat162 p = __float22bfloat162_rn(make_float2(c0, c1));
                *(__nv_bfloat162*)(g_hb + ((size_t)((n0 + rA) * NEV + e)) * DD + cb) = p;
            }
            if (n0 + rA + 8 < NN) {
                __nv_bfloat162 p = __float22bfloat162_rn(make_float2(c2, c3));
                *(__nv_bfloat162*)(g_hb + ((size_t)((n0 + rA + 8) * NEV + e)) * DD + cb) = p;
            }
            float a10 = a_sm[0][cb], a11 = a_sm[0][cb + 1];
            float a20 = a_sm[1][cb], a21 = a_sm[1][cb + 1];
            s1a += c0 * a10 + c1 * a11;
            s2a += c0 * a20 + c1 * a21;
            s1b += c2 * a10 + c3 * a11;
            s2b += c2 * a20 + c3 * a21;
        }
#pragma unroll
        for (int off = 1; off < 4; off <<= 1) {
            s1a += __shfl_xor_sync(0xffffffffu, s1a, off);
            s2a += __shfl_xor_sync(0xffffffffu, s2a, off);
            s1b += __shfl_xor_sync(0xffffffffu, s1b, off);
            s2b += __shfl_xor_sync(0xffffffffu, s2b, off);
        }
        if (qtr == 0) {
            atomicAdd(&s1_sm[rA], s1a);
            atomicAdd(&s2_sm[rA], s2a);
            atomicAdd(&s1_sm[rA + 8], s1b);
            atomicAdd(&s2_sm[rA + 8], s2b);
        }
    }
    __syncthreads();
    if (tid < 128 && n0 + tid < NN) {
        g_ssrc[(n0 + tid) * NEV + e] = s1_sm[tid];
        g_sdst[(n0 + tid) * NEV + e] = s2_sm[tid];
    }
}

// ---------------- K3: degree histogram -----------------------------------
__global__ void __launch_bounds__(256) k_hist(const int* __restrict__ row) {
    int k = blockIdx.x * blockDim.x + threadIdx.x;
    if (k >= ETOT) return;
    int src = (k < EE) ? row[k] : (k - EE);
    atomicAdd(&g_cnt[src], 1);
}

// ---------------- K4a: per-block exclusive scan of g_cnt -----------------
__global__ void __launch_bounds__(1024) k_scan1() {
    int i = blockIdx.x * 1024 + threadIdx.x;
    int lane = threadIdx.x & 31, wid = threadIdx.x >> 5;
    int v = (i < NN) ? g_cnt[i] : 0;
    int s = v;
#pragma unroll
    for (int off = 1; off < 32; off <<= 1) {
        int t = __shfl_up_sync(0xffffffffu, s, off);
        if (lane >= off) s += t;
    }
    __shared__ int wsum[32];
    if (lane == 31) wsum[wid] = s;
    __syncthreads();
    if (wid == 0) {
        int t = wsum[lane];
        int sc = t;
#pragma unroll
        for (int off = 1; off < 32; off <<= 1) {
            int u = __shfl_up_sync(0xffffffffu, sc, off);
            if (lane >= off) sc += u;
        }
        wsum[lane] = sc - t;
    }
    __syncthreads();
    int excl = s - v + wsum[wid];
    if (i < NN) g_rowptr[i] = excl;
    if (threadIdx.x == 1023) g_bsum[blockIdx.x] = excl + v;
}

// ---------------- K4b: scan block sums -----------------------------------
__global__ void k_scan2() {
    if (threadIdx.x == 0) {
        int run = 0;
        for (int i = 0; i < NBLK; i++) {
            int t = g_bsum[i];
            g_boff[i] = run;
            run += t;
        }
    }
}

// ---------------- K4c: add block offsets, init cursors -------------------
__global__ void __launch_bounds__(1024) k_scan3() {
    int i = blockIdx.x * 1024 + threadIdx.x;
    if (i < NN) {
        int r = g_rowptr[i] + g_boff[i >> 10];
        g_rowptr[i] = r;
        g_cursor[i] = r;
    }
}

// ---------------- K5: CSR fill + per-env global max (fused) --------------
__global__ void __launch_bounds__(256) k_fill_max(const int* __restrict__ row,
                                                  const int* __restrict__ col) {
    float m0 = -3.4e38f, m1 = -3.4e38f, m2 = -3.4e38f, m3 = -3.4e38f;
    for (int k = blockIdx.x * blockDim.x + threadIdx.x; k < ETOT;
         k += gridDim.x * blockDim.x) {
        int src, dst;
        if (k < EE) { src = row[k]; dst = col[k]; }
        else        { src = dst = k - EE; }
        int slot = atomicAdd(&g_cursor[src], 1);
        g_csrdst[slot] = dst;
        float4 sa = ((const float4*)g_ssrc)[src];
        float4 sb = ((const float4*)g_sdst)[dst];
        m0 = fmaxf(m0, lrelu(sa.x + sb.x));
        m1 = fmaxf(m1, lrelu(sa.y + sb.y));
        m2 = fmaxf(m2, lrelu(sa.z + sb.z));
        m3 = fmaxf(m3, lrelu(sa.w + sb.w));
    }
    int lane = threadIdx.x & 31, wid = threadIdx.x >> 5;
#pragma unroll
    for (int off = 16; off > 0; off >>= 1) {
        m0 = fmaxf(m0, __shfl_xor_sync(0xffffffffu, m0, off));
        m1 = fmaxf(m1, __shfl_xor_sync(0xffffffffu, m1, off));
        m2 = fmaxf(m2, __shfl_xor_sync(0xffffffffu, m2, off));
        m3 = fmaxf(m3, __shfl_xor_sync(0xffffffffu, m3, off));
    }
    __shared__ float sm[8][NEV];
    if (lane == 0) { sm[wid][0] = m0; sm[wid][1] = m1; sm[wid][2] = m2; sm[wid][3] = m3; }
    __syncthreads();
    if (threadIdx.x < NEV) {
        int e = threadIdx.x;
        float mm = -3.4e38f;
#pragma unroll
        for (int wdx = 0; wdx < 8; wdx++) mm = fmaxf(mm, sm[wdx][e]);
        atomicMax(&g_max_enc[e], enc_f(mm));
    }
}

// ---------------- K7: fused bf16 gather-aggregate + combine + residual ---
__global__ void __launch_bounds__(256) k_agg(const float* __restrict__ x,
                                             const float* __restrict__ ew,
                                             float* __restrict__ out) {
    int n    = (blockIdx.x * blockDim.x + threadIdx.x) >> 5;
    int lane = threadIdx.x & 31;
    if (n >= NN) return;

    float4 ss = ((const float4*)g_ssrc)[n];
    float M0 = dec_u(g_max_enc[0]);
    float M1 = dec_u(g_max_enc[1]);
    float M2 = dec_u(g_max_enc[2]);
    float M3 = dec_u(g_max_enc[3]);

    int start = g_rowptr[n];
    int deg   = g_cnt[n];

    float4 a0 = make_float4(0.f, 0.f, 0.f, 0.f);
    float4 a1 = a0, a2 = a0, a3 = a0;
    float d0 = 0.f, d1 = 0.f, d2 = 0.f, d3 = 0.f;

#pragma unroll 4
    for (int j = 0; j < deg; j++) {
        int dst = g_csrdst[start + j];
        float4 sd = ((const float4*)g_sdst)[dst];
        float t0 = __expf(lrelu(ss.x + sd.x) - M0);
        float t1 = __expf(lrelu(ss.y + sd.y) - M1);
        float t2 = __expf(lrelu(ss.z + sd.z) - M2);
        float t3 = __expf(lrelu(ss.w + sd.w) - M3);

        const uint2* hp = (const uint2*)(g_hb + (size_t)dst * (NEV * DD));
        uint2 u0 = hp[lane];           // env 0: 4 bf16 (d = lane*4..lane*4+3)
        uint2 u1 = hp[32 + lane];      // env 1
        uint2 u2 = hp[64 + lane];      // env 2
        uint2 u3 = hp[96 + lane];      // env 3

        float2 p0a = __bfloat1622float2(*(__nv_bfloat162*)&u0.x);
        float2 p0b = __bfloat1622float2(*(__nv_bfloat162*)&u0.y);
        float2 p1a = __bfloat1622float2(*(__nv_bfloat162*)&u1.x);
        float2 p1b = __bfloat1622float2(*(__nv_bfloat162*)&u1.y);
        float2 p2a = __bfloat1622float2(*(__nv_bfloat162*)&u2.x);
        float2 p2b = __bfloat1622float2(*(__nv_bfloat162*)&u2.y);
        float2 p3a = __bfloat1622float2(*(__nv_bfloat162*)&u3.x);
        float2 p3b = __bfloat1622float2(*(__nv_bfloat162*)&u3.y);

        a0.x += t0 * p0a.x; a0.y += t0 * p0a.y; a0.z += t0 * p0b.x; a0.w += t0 * p0b.y;
        a1.x += t1 * p1a.x; a1.y += t1 * p1a.y; a1.z += t1 * p1b.x; a1.w += t1 * p1b.y;
        a2.x += t2 * p2a.x; a2.y += t2 * p2a.y; a2.z += t2 * p2b.x; a2.w += t2 * p2b.y;
        a3.x += t3 * p3a.x; a3.y += t3 * p3a.y; a3.z += t3 * p3b.x; a3.w += t3 * p3b.y;
        d0 += t0; d1 += t1; d2 += t2; d3 += t3;
    }

    float4 ewv = ((const float4*)ew)[n];
    float w0 = ewv.x / (d0 + EPSF);
    float w1 = ewv.y / (d1 + EPSF);
    float w2 = ewv.z / (d2 + EPSF);
    float w3 = ewv.w / (d3 + EPSF);

    float4 o = ((const float4*)x)[n * 32 + lane];
    o.x += w0 * a0.x + w1 * a1.x + w2 * a2.x + w3 * a3.x;
    o.y += w0 * a0.y + w1 * a1.y + w2 * a2.y + w3 * a3.y;
    o.z += w0 * a0.z + w1 * a1.z + w2 * a2.z + w3 * a3.z;
    o.w += w0 * a0.w + w1 * a1.w + w2 * a2.w + w3 * a3.w;
    ((float4*)out)[n * 32 + lane] = o;
}

// ---------------- launch --------------------------------------------------
extern "C" void kernel_launch(void* const* d_in, const int* in_sizes, int n_in,
                              void* d_out, int out_size) {
    const float* x   = (const float*)d_in[0];
    const int*   adj = (const int*)d_in[1];
    const float* ew  = (const float*)d_in[2];
    const float* w   = (const float*)d_in[3];
    const float* a   = (const float*)d_in[4];
    const int* row = adj;
    const int* col = adj + EE;
    float* out = (float*)d_out;

    k_zero<<<(NN + 255) / 256, 256>>>();

    dim3 g1((NN + 127) / 128, NEV);
    k_gemm<<<g1, 256>>>(x, w, a);

    k_hist<<<(ETOT + 255) / 256, 256>>>(row);
    k_scan1<<<NBLK, 1024>>>();
    k_scan2<<<1, 32>>>();
    k_scan3<<<NBLK, 1024>>>();

    k_fill_max<<<1024, 256>>>(row, col);

    k_agg<<<(NN * 32 + 255) / 256, 256>>>(x, ew, out);
}